// round 16
// baseline (speedup 1.0000x reference)
#include <cuda_runtime.h>
#include <cuda_fp16.h>
#include <math.h>
#include <stdint.h>

#define SEQ  2048
#define DM   4096
#define NH   16
#define DH   256
#define DFF  16384
#define LDQKV (3 * DM)

#define BM 128
#define BN 128
#define BK 32          // halves per k-step
#define STG 4
#define ROWH 40        // padded row length in halves (80B)
#define A_H (BM * ROWH)        // 5120 halves
#define B_H (BN * ROWH)        // 5120 halves
#define SLOT_H (A_H + B_H)     // 10240 halves
#define SLOT_B (SLOT_H * 2)    // 20480 bytes
#define SMEM_B (STG * SLOT_B)  // 81920 bytes -> 2 CTAs/SM

// ---- flash attention tiles (2-CTA/SM config) ----
#define FBM 64                  // q rows per CTA work item
#define FBJ 32                  // keys per j-tile
#define FROWK 264               // Q/K smem row halves (256 + 8 pad)
#define FROWV 40                // V^T smem row halves (32 + 8 pad)
#define FQ_H (FBM * FROWK)      // 16896 halves
#define FK_H (FBJ * FROWK)      // 8448 halves per stage
#define FV_H (DH * FROWV)       // 10240 halves per stage
#define FK_BASE FQ_H
#define FV_BASE (FQ_H + 2 * FK_H)
#define FLASH_SMEM ((FQ_H + 2 * FK_H + 2 * FV_H) * 2)   // 108544 B -> 2 CTAs/SM

// ---------------- device scratch ----------------
__device__ __half g_xn [(size_t)SEQ * DM];
__device__ __half g_qkv[(size_t)SEQ * LDQKV];
__device__ __half g_vt [(size_t)DM * SEQ];          // v^T: [h*256+d][T]
__device__ __half g_av [(size_t)SEQ * DM];
__device__ float  g_ao [(size_t)SEQ * DM];
__device__ __half g_f1 [(size_t)SEQ * DFF];
// fp16 transposed weights [N][K]
__device__ __half g_wqkv[(size_t)LDQKV * DM];
__device__ __half g_wo  [(size_t)DM * DM];
__device__ __half g_w1t [(size_t)DFF * DM];
__device__ __half g_w2t [(size_t)DM * DFF];

// ---------------- helpers ----------------
__device__ __forceinline__ float gelu_f(float x) {
    float x3 = x * x * x;
    return x / (1.0f + __expf(-(1.5957691216057308f * x + 0.07135481627f * x3)));
}
__device__ __forceinline__ unsigned smem_u32(const void* p) {
    return (unsigned)__cvta_generic_to_shared(p);
}

#define CP_A16(saddr, gptr) \
    asm volatile("cp.async.cg.shared.global [%0], [%1], 16;\n" :: "r"(saddr), "l"(gptr))
#define CP_COMMIT() asm volatile("cp.async.commit_group;\n" ::: "memory")
#define CP_WAIT1()  asm volatile("cp.async.wait_group 1;\n" ::: "memory")
#define CP_WAIT2()  asm volatile("cp.async.wait_group 2;\n" ::: "memory")
#define CP_WAIT0()  asm volatile("cp.async.wait_group 0;\n" ::: "memory")

#define LDSM4(r, addr) \
    asm volatile("ldmatrix.sync.aligned.m8n8.x4.shared.b16 {%0,%1,%2,%3}, [%4];" \
        : "=r"((r)[0]), "=r"((r)[1]), "=r"((r)[2]), "=r"((r)[3]) : "r"(addr))

__device__ __forceinline__ void mma16(float c[4], const uint32_t a[4], uint32_t b0, uint32_t b1) {
    asm volatile(
        "mma.sync.aligned.m16n8k16.row.col.f32.f16.f16.f32 "
        "{%0,%1,%2,%3},{%4,%5,%6,%7},{%8,%9},{%0,%1,%2,%3};"
        : "+f"(c[0]), "+f"(c[1]), "+f"(c[2]), "+f"(c[3])
        : "r"(a[0]), "r"(a[1]), "r"(a[2]), "r"(a[3]), "r"(b0), "r"(b1));
}

template <typename T> __device__ __forceinline__ void store2(T* p, float x, float y);
template <> __device__ __forceinline__ void store2<float>(float* p, float x, float y) {
    *(float2*)p = make_float2(x, y);
}
template <> __device__ __forceinline__ void store2<__half>(__half* p, float x, float y) {
    *(__half2*)p = __floats2half2_rn(x, y);
}

// ================= FP16 GEMM: C[M][N] = A[M][K] @ BT[N][K]^T (R10-proven) =================
template <int EPI, typename OutT>
__global__ __launch_bounds__(128, 2)
void gemm16(const __half* __restrict__ A, const __half* __restrict__ BT,
            OutT* __restrict__ C, int K, int lda, int ldb, int ldc,
            const float* __restrict__ bias, const float* __restrict__ addend) {
    extern __shared__ __half smh[];
    int m0 = blockIdx.y * BM, n0 = blockIdx.x * BN;
    int tid = threadIdx.x, warp = tid >> 5, lane = tid & 31;
    int nk = K / BK;

    uint32_t sb = smem_u32(smh);
    const __half* Ag = A + (size_t)(m0 + (tid >> 2)) * lda + (tid & 3) * 8;
    const __half* Bg = BT + (size_t)(n0 + (tid >> 2)) * ldb + (tid & 3) * 8;
    uint32_t Ad = sb + ((tid >> 2) * ROWH + (tid & 3) * 8) * 2;
    uint32_t Bd = sb + (A_H + (tid >> 2) * ROWH + (tid & 3) * 8) * 2;

    auto issue = [&](int t) {
        uint32_t off = (t & 3) * SLOT_B;
        int k0 = t * BK;
#pragma unroll
        for (int i = 0; i < 4; i++)
            CP_A16(Ad + off + i * 32 * ROWH * 2, Ag + (size_t)i * 32 * lda + k0);
#pragma unroll
        for (int i = 0; i < 4; i++)
            CP_A16(Bd + off + i * 32 * ROWH * 2, Bg + (size_t)i * 32 * ldb + k0);
    };

    issue(0); CP_COMMIT();
    if (nk > 1) issue(1);
    CP_COMMIT();
    if (nk > 2) issue(2);
    CP_COMMIT();

    int wm = (warp >> 1) * 64, wn = (warp & 1) * 64;
    uint32_t aAddr = sb + ((wm + (lane & 15)) * ROWH + (lane >> 4) * 8) * 2;
    uint32_t bAddr = sb + A_H * 2 +
                     ((wn + (lane & 7) + ((lane >> 4) & 1) * 8) * ROWH + ((lane >> 3) & 1) * 8) * 2;

    float acc[4][8][4];
#pragma unroll
    for (int i = 0; i < 4; i++)
#pragma unroll
        for (int j = 0; j < 8; j++)
#pragma unroll
            for (int q = 0; q < 4; q++) acc[i][j][q] = 0.f;

    for (int t = 0; t < nk; t++) {
        CP_WAIT2();
        __syncthreads();
        int u = t + 3;
        if (u < nk) issue(u);
        CP_COMMIT();

        uint32_t so = (t & 3) * SLOT_B;
#pragma unroll
        for (int ks = 0; ks < 2; ks++) {
            uint32_t a[4][4], b[4][4];
#pragma unroll
            for (int mt = 0; mt < 4; mt++)
                LDSM4(a[mt], aAddr + so + mt * (16 * ROWH * 2) + ks * 32);
#pragma unroll
            for (int p = 0; p < 4; p++)
                LDSM4(b[p], bAddr + so + p * (16 * ROWH * 2) + ks * 32);
#pragma unroll
            for (int mt = 0; mt < 4; mt++)
#pragma unroll
                for (int nt = 0; nt < 8; nt++)
                    mma16(acc[mt][nt], a[mt], b[nt >> 1][(nt & 1) * 2], b[nt >> 1][(nt & 1) * 2 + 1]);
        }
    }

    CP_WAIT0();
    __syncthreads();

    int r = lane >> 2, c2 = 2 * (lane & 3);
#pragma unroll
    for (int mt = 0; mt < 4; mt++)
#pragma unroll
        for (int nt = 0; nt < 8; nt++) {
            int gm0 = m0 + wm + mt * 16 + r;
            int gn = n0 + wn + nt * 8 + c2;
#pragma unroll
            for (int h = 0; h < 2; h++) {
                int gm = gm0 + h * 8;
                float vx = acc[mt][nt][h * 2], vy = acc[mt][nt][h * 2 + 1];
                if (EPI == 2 || EPI == 3) {
                    const float2 bb = *(const float2*)(bias + gn);
                    vx += bb.x; vy += bb.y;
                }
                if (EPI == 2) { vx = gelu_f(vx); vy = gelu_f(vy); }
                if (EPI == 3) {
                    const float2 ad = *(const float2*)(addend + (size_t)gm * ldc + gn);
                    vx += ad.x; vy += ad.y;
                }
                store2<OutT>(C + (size_t)gm * ldc + gn, vx, vy);
            }
        }
}

// ================= fused flash attention: FBM=64/FBJ=32, 128 threads, 2 CTAs/SM =================
// CTA (px, h): processes m-tile (31-px) then (px). Pair cost = 66 tiles for every CTA.
__global__ __launch_bounds__(128, 2)
void flash16(const __half* __restrict__ qkv, const __half* __restrict__ vt,
             const float* __restrict__ ab, __half* __restrict__ av) {
    int h = blockIdx.y;
    extern __shared__ __half smh[];
    uint32_t sb = smem_u32(smh);
    int tid = threadIdx.x, warp = tid >> 5, lane = tid & 31;

    const __half* Kg = qkv + DM + (size_t)h * DH;
    const __half* Vg = vt + (size_t)h * DH * SEQ;
    const __half* Qg = qkv + (size_t)h * DH;

    int nmt = SEQ / FBM;                      // 32

    for (int item = 0; item < 2; item++) {
        int mt = item == 0 ? (nmt - 1 - (int)blockIdx.x) : (int)blockIdx.x;
        int m0 = mt * FBM;
        int nj = (m0 + FBM) / FBJ;            // 2*mt + 2

        __syncthreads();   // all warps done with smem from previous item

        // Q load: 64 rows x 32 chunks(16B) = 2048 / 128thr = 16 each
        {
            int row = tid >> 1, cb = (tid & 1) * 16;
#pragma unroll
            for (int i = 0; i < 16; i++) {
                int ch = cb + i;
                CP_A16(sb + (row * FROWK + ch * 8) * 2,
                       Qg + (size_t)(m0 + row) * LDQKV + ch * 8);
            }
        }

        auto issue = [&](int t) {
            int buf = t & 1;
            int j0 = t * FBJ;
            // K: 32 rows x 32 chunks = 1024 / 128 = 8 per thread
            int krow = tid >> 2, kc0 = (tid & 3) * 8;
#pragma unroll
            for (int i = 0; i < 8; i++) {
                int ch = kc0 + i;
                CP_A16(sb + (FK_BASE + buf * FK_H + krow * FROWK + ch * 8) * 2,
                       Kg + (size_t)(j0 + krow) * LDQKV + ch * 8);
            }
            // V^T: 256 rows x 4 chunks = 1024 / 128 = 8 per thread (2 rows x 4)
            int vr = tid << 1;
#pragma unroll
            for (int r2 = 0; r2 < 2; r2++)
#pragma unroll
                for (int ch = 0; ch < 4; ch++)
                    CP_A16(sb + (FV_BASE + buf * FV_H + (vr + r2) * FROWV + ch * 8) * 2,
                           Vg + (size_t)(vr + r2) * SEQ + j0 + ch * 8);
        };

        issue(0); CP_COMMIT();
        if (nj > 1) issue(1);
        CP_COMMIT();

        float o[32][4];
#pragma unroll
        for (int i = 0; i < 32; i++)
#pragma unroll
            for (int q = 0; q < 4; q++) o[i][q] = 0.f;
        float mrun0 = -1e30f, mrun1 = -1e30f;
        float lrun0 = 0.f, lrun1 = 0.f;

        uint32_t aQ = sb + ((16 * warp + (lane & 15)) * FROWK + (lane >> 4) * 8) * 2;
        int r = lane >> 2, c = lane & 3;
        int row0 = m0 + 16 * warp + r;
        const float scl = 1.0f / 16.0f;

        for (int t = 0; t < nj; t++) {
            CP_WAIT1();
            __syncthreads();
            int j0 = t * FBJ;
            uint32_t kb = sb + (FK_BASE + (t & 1) * FK_H) * 2;
            uint32_t vb = sb + (FV_BASE + (t & 1) * FV_H) * 2;

            // ---- S = Q K^T (16 x 32 per warp) ----
            float s[4][4];
#pragma unroll
            for (int nt = 0; nt < 4; nt++)
#pragma unroll
                for (int q = 0; q < 4; q++) s[nt][q] = 0.f;
#pragma unroll 4
            for (int ks = 0; ks < 16; ks++) {
                uint32_t aq[4];
                LDSM4(aq, aQ + ks * 32);
#pragma unroll
                for (int p = 0; p < 2; p++) {
                    uint32_t bk[4];
                    LDSM4(bk, kb + ((p * 16 + (lane & 7) + ((lane >> 4) & 1) * 8) * FROWK
                                    + ((lane >> 3) & 1) * 8 + ks * 16) * 2);
                    mma16(s[2 * p],     aq, bk[0], bk[1]);
                    mma16(s[2 * p + 1], aq, bk[2], bk[3]);
                }
            }

            // ---- scale + bias + causal mask + online softmax ----
            bool domask = (t >= nj - 2);
            float rmax0 = -1e30f, rmax1 = -1e30f;
#pragma unroll
            for (int nt = 0; nt < 4; nt++) {
                int j = j0 + nt * 8 + 2 * c;
                const float2 b0 = *(const float2*)(ab + (size_t)row0 * SEQ + j);
                const float2 b1 = *(const float2*)(ab + (size_t)(row0 + 8) * SEQ + j);
                s[nt][0] = s[nt][0] * scl + b0.x;
                s[nt][1] = s[nt][1] * scl + b0.y;
                s[nt][2] = s[nt][2] * scl + b1.x;
                s[nt][3] = s[nt][3] * scl + b1.y;
                if (domask) {
                    if (j     > row0)     s[nt][0] = -1e30f;
                    if (j + 1 > row0)     s[nt][1] = -1e30f;
                    if (j     > row0 + 8) s[nt][2] = -1e30f;
                    if (j + 1 > row0 + 8) s[nt][3] = -1e30f;
                }
                rmax0 = fmaxf(rmax0, fmaxf(s[nt][0], s[nt][1]));
                rmax1 = fmaxf(rmax1, fmaxf(s[nt][2], s[nt][3]));
            }
            rmax0 = fmaxf(rmax0, __shfl_xor_sync(0xffffffffu, rmax0, 1));
            rmax0 = fmaxf(rmax0, __shfl_xor_sync(0xffffffffu, rmax0, 2));
            rmax1 = fmaxf(rmax1, __shfl_xor_sync(0xffffffffu, rmax1, 1));
            rmax1 = fmaxf(rmax1, __shfl_xor_sync(0xffffffffu, rmax1, 2));
            float mnew0 = fmaxf(mrun0, rmax0);
            float mnew1 = fmaxf(mrun1, rmax1);
            float corr0 = __expf(mrun0 - mnew0);
            float corr1 = __expf(mrun1 - mnew1);
            mrun0 = mnew0; mrun1 = mnew1;

            uint32_t ph[4][2];
            float rs0 = 0.f, rs1 = 0.f;
#pragma unroll
            for (int nt = 0; nt < 4; nt++) {
                float p0 = __expf(s[nt][0] - mnew0);
                float p1 = __expf(s[nt][1] - mnew0);
                float p2 = __expf(s[nt][2] - mnew1);
                float p3 = __expf(s[nt][3] - mnew1);
                rs0 += p0 + p1; rs1 += p2 + p3;
                __half2 h0 = __floats2half2_rn(p0, p1);
                __half2 h1 = __floats2half2_rn(p2, p3);
                ph[nt][0] = *(uint32_t*)&h0;
                ph[nt][1] = *(uint32_t*)&h1;
            }
            rs0 += __shfl_xor_sync(0xffffffffu, rs0, 1);
            rs0 += __shfl_xor_sync(0xffffffffu, rs0, 2);
            rs1 += __shfl_xor_sync(0xffffffffu, rs1, 1);
            rs1 += __shfl_xor_sync(0xffffffffu, rs1, 2);
            lrun0 = lrun0 * corr0 + rs0;
            lrun1 = lrun1 * corr1 + rs1;
#pragma unroll
            for (int p = 0; p < 32; p++) {
                o[p][0] *= corr0; o[p][1] *= corr0;
                o[p][2] *= corr1; o[p][3] *= corr1;
            }

            // ---- O += P V  (P fragments = S C-fragments repacked) ----
#pragma unroll
            for (int kk = 0; kk < 2; kk++) {
                uint32_t a[4] = { ph[2 * kk][0], ph[2 * kk][1], ph[2 * kk + 1][0], ph[2 * kk + 1][1] };
#pragma unroll
                for (int p = 0; p < 16; p++) {
                    uint32_t bv[4];
                    LDSM4(bv, vb + ((p * 16 + (lane & 7) + ((lane >> 4) & 1) * 8) * FROWV
                                    + ((lane >> 3) & 1) * 8 + kk * 16) * 2);
                    mma16(o[2 * p],     a, bv[0], bv[1]);
                    mma16(o[2 * p + 1], a, bv[2], bv[3]);
                }
            }

            __syncthreads();
            if (t + 2 < nj) issue(t + 2);
            CP_COMMIT();
        }

        // ---- normalize + write ----
        float inv0 = 1.0f / lrun0, inv1 = 1.0f / lrun1;
        __half* a0 = av + (size_t)row0 * DM + h * DH;
        __half* a1 = av + (size_t)(row0 + 8) * DM + h * DH;
#pragma unroll
        for (int p = 0; p < 32; p++) {
            int d = p * 8 + 2 * c;
            *(__half2*)(a0 + d) = __floats2half2_rn(o[p][0] * inv0, o[p][1] * inv0);
            *(__half2*)(a1 + d) = __floats2half2_rn(o[p][2] * inv1, o[p][3] * inv1);
        }
        CP_WAIT0();   // drain trailing groups before reusing smem
    }
}

// ================= weight transpose + fp32->fp16, full-sector stores (R10-proven) =================
__global__ __launch_bounds__(256)
void trw(const float* __restrict__ src, __half* __restrict__ dst, int K, int N) {
    __shared__ float tile[64][33];
    int k0 = blockIdx.y * 64, n0 = blockIdx.x * 32;
    int tx = threadIdx.x, ty = threadIdx.y;
#pragma unroll
    for (int i = 0; i < 8; i++)
        tile[ty + i * 8][tx] = src[(size_t)(k0 + ty + i * 8) * N + n0 + tx];
    __syncthreads();
#pragma unroll
    for (int i = 0; i < 4; i++) {
        int n = ty + i * 8;
        __half2 h = __floats2half2_rn(tile[2 * tx][n], tile[2 * tx + 1][n]);
        *(__half2*)(dst + (size_t)(n0 + n) * K + k0 + 2 * tx) = h;
    }
}

// ================= v transpose (R5-proven): vt[c][T] = qkv[T][2*DM + c] =================
__global__ void trv(const __half* __restrict__ qkv, __half* __restrict__ vt) {
    __shared__ __half tile[32][33];
    int c0 = blockIdx.x * 32, T0 = blockIdx.y * 32;
    int tx = threadIdx.x, ty = threadIdx.y;
#pragma unroll
    for (int i = 0; i < 4; i++)
        tile[ty + i * 8][tx] = qkv[(size_t)(T0 + ty + i * 8) * LDQKV + 2 * DM + c0 + tx];
    __syncthreads();
#pragma unroll
    for (int i = 0; i < 4; i++)
        vt[(size_t)(c0 + ty + i * 8) * SEQ + T0 + tx] = tile[tx][ty + i * 8];
}

// ================= layernorm -> half (single-pass, register-cached; R15-proven) =================
__global__ void ln_kernel(const float* __restrict__ x, const float* __restrict__ sc,
                          const float* __restrict__ of, __half* __restrict__ xn) {
    int row = blockIdx.x;
    const float4* xr = (const float4*)(x + (size_t)row * DM);
    __half* xo = xn + (size_t)row * DM;
    __shared__ float redS[256];
    __shared__ float redQ[256];
    int tid = threadIdx.x;

    float4 v[4];
    float s = 0.f, q = 0.f;
#pragma unroll
    for (int i = 0; i < 4; i++) {
        v[i] = xr[tid + i * 256];
        s += v[i].x + v[i].y + v[i].z + v[i].w;
        q += v[i].x * v[i].x + v[i].y * v[i].y + v[i].z * v[i].z + v[i].w * v[i].w;
    }
    redS[tid] = s; redQ[tid] = q;
    __syncthreads();
    for (int st = 128; st > 0; st >>= 1) {
        if (tid < st) { redS[tid] += redS[tid + st]; redQ[tid] += redQ[tid + st]; }
        __syncthreads();
    }
    float mean = redS[0] * (1.0f / DM);
    float var = redQ[0] * (1.0f / DM) - mean * mean;
    float rstd = rsqrtf(var + 1e-5f);

#pragma unroll
    for (int i = 0; i < 4; i++) {
        int base = (tid + i * 256) * 4;
        const float4 g = *(const float4*)(sc + base);
        const float4 o = *(const float4*)(of + base);
        __half2 h0 = __floats2half2_rn(g.x * rstd * (v[i].x - mean) + o.x,
                                       g.y * rstd * (v[i].y - mean) + o.y);
        __half2 h1 = __floats2half2_rn(g.z * rstd * (v[i].z - mean) + o.z,
                                       g.w * rstd * (v[i].w - mean) + o.w);
        uint2 pk = make_uint2(*(uint32_t*)&h0, *(uint32_t*)&h1);
        *(uint2*)(xo + base) = pk;
    }
}

// ================= RoPE on half q,k =================
__global__ void rope_kernel(__half* __restrict__ qkv) {
    int t = blockIdx.x, tid = threadIdx.x;
    __shared__ float ss[32], cc[32];
    if (tid < 32) {
        double inv = pow(10000.0, -((double)(2 * tid)) / 64.0);
        double a = (double)t * inv;
        ss[tid] = (float)sin(a); cc[tid] = (float)cos(a);
    }
    __syncthreads();
    int head = tid >> 5, i = tid & 31;
    float s = ss[i], co = cc[i];
    size_t qoff = (size_t)t * LDQKV + head * DH + 2 * i;
    size_t koff = qoff + DM;
    float q0 = __half2float(qkv[qoff]), q1 = __half2float(qkv[qoff + 1]);
    qkv[qoff]     = __float2half(q0 * co - q1 * s);
    qkv[qoff + 1] = __float2half(q1 * co + q0 * s);
    float k0 = __half2float(qkv[koff]), k1 = __half2float(qkv[koff + 1]);
    qkv[koff]     = __float2half(k0 * co - k1 * s);
    qkv[koff + 1] = __float2half(k1 * co + k0 * s);
}

// ================= launch (EXACT R10/R15 schedule & topology) =================
extern "C" void kernel_launch(void* const* d_in, const int* in_sizes, int n_in,
                              void* d_out, int out_size) {
    const float* x   = (const float*)d_in[0];
    const float* ab  = (const float*)d_in[1];
    const float* lns = (const float*)d_in[2];
    const float* lno = (const float*)d_in[3];
    const float* wq  = (const float*)d_in[4];
    const float* wk  = (const float*)d_in[5];
    const float* wv  = (const float*)d_in[6];
    const float* wo  = (const float*)d_in[7];
    const float* w1  = (const float*)d_in[8];
    const float* b1  = (const float*)d_in[9];
    const float* w2  = (const float*)d_in[10];
    const float* b2  = (const float*)d_in[11];
    float* out = (float*)d_out;

    __half *xn, *qkv, *vt, *av, *f1, *wqkv16, *wo16, *w1t16, *w2t16;
    float *ao;
    cudaGetSymbolAddress((void**)&xn,     g_xn);
    cudaGetSymbolAddress((void**)&qkv,    g_qkv);
    cudaGetSymbolAddress((void**)&vt,     g_vt);
    cudaGetSymbolAddress((void**)&av,     g_av);
    cudaGetSymbolAddress((void**)&ao,     g_ao);
    cudaGetSymbolAddress((void**)&f1,     g_f1);
    cudaGetSymbolAddress((void**)&wqkv16, g_wqkv);
    cudaGetSymbolAddress((void**)&wo16,   g_wo);
    cudaGetSymbolAddress((void**)&w1t16,  g_w1t);
    cudaGetSymbolAddress((void**)&w2t16,  g_w2t);

    cudaFuncSetAttribute(gemm16<0, __half>, cudaFuncAttributeMaxDynamicSharedMemorySize, SMEM_B);
    cudaFuncSetAttribute(gemm16<0, float>,  cudaFuncAttributeMaxDynamicSharedMemorySize, SMEM_B);
    cudaFuncSetAttribute(gemm16<2, __half>, cudaFuncAttributeMaxDynamicSharedMemorySize, SMEM_B);
    cudaFuncSetAttribute(gemm16<3, float>,  cudaFuncAttributeMaxDynamicSharedMemorySize, SMEM_B);
    cudaFuncSetAttribute(flash16,           cudaFuncAttributeMaxDynamicSharedMemorySize, FLASH_SMEM);

    // fork/join: FFN-hidden branch on s1, attention branch on the capture (default) stream
    cudaStream_t s1;
    cudaStreamCreateWithFlags(&s1, cudaStreamNonBlocking);
    cudaEvent_t evRoot, evLN, evF1;
    cudaEventCreateWithFlags(&evRoot, cudaEventDisableTiming);
    cudaEventCreateWithFlags(&evLN,   cudaEventDisableTiming);
    cudaEventCreateWithFlags(&evF1,   cudaEventDisableTiming);

    dim3 tb(32, 8);
    cudaEventRecord(evRoot, 0);
    cudaStreamWaitEvent(s1, evRoot, 0);

    // ---- s1 branch: w1/w2 prep, then FFN1 after LN ----
    trw<<<dim3(DFF / 32, DM / 64), tb, 0, s1>>>(w1, w1t16, DM, DFF);
    trw<<<dim3(DM / 32, DFF / 64), tb, 0, s1>>>(w2, w2t16, DFF, DM);

    // ---- s0: attention-side weight prep + LN ----
    trw<<<dim3(DM / 32, DM / 64), tb>>>(wq, wqkv16, DM, DM);
    trw<<<dim3(DM / 32, DM / 64), tb>>>(wk, wqkv16 + (size_t)DM * DM, DM, DM);
    trw<<<dim3(DM / 32, DM / 64), tb>>>(wv, wqkv16 + (size_t)2 * DM * DM, DM, DM);
    trw<<<dim3(DM / 32, DM / 64), tb>>>(wo, wo16, DM, DM);
    ln_kernel<<<SEQ, 256>>>(x, lns, lno, xn);
    cudaEventRecord(evLN, 0);

    // s1: FFN1 after LN
    cudaStreamWaitEvent(s1, evLN, 0);
    gemm16<2, __half><<<dim3(DFF / BN, SEQ / BM), 128, SMEM_B, s1>>>(
        xn, w1t16, f1, DM, DM, DM, DFF, b1, nullptr);
    cudaEventRecord(evF1, s1);

    // ---- s0: attention chain ----
    gemm16<0, __half><<<dim3(LDQKV / BN, SEQ / BM), 128, SMEM_B>>>(
        xn, wqkv16, qkv, DM, DM, DM, LDQKV, nullptr, nullptr);
    rope_kernel<<<SEQ, 512>>>(qkv);
    trv<<<dim3(DM / 32, SEQ / 32), tb>>>(qkv, vt);
    flash16<<<dim3(SEQ / FBM / 2, NH), 128, FLASH_SMEM>>>(qkv, vt, ab, av);
    gemm16<0, float><<<dim3(DM / BN, SEQ / BM), 128, SMEM_B>>>(
        av, wo16, ao, DM, DM, DM, DM, nullptr, nullptr);

    // join and final FFN2 (+bias +residual)
    cudaStreamWaitEvent(0, evF1, 0);
    gemm16<3, float><<<dim3(DM / BN, SEQ / BM), 128, SMEM_B>>>(
        f1, w2t16, out, DFF, DFF, DFF, DM, b2, ao);
}

// round 17
// speedup vs baseline: 1.0276x; 1.0276x over previous
#include <cuda_runtime.h>
#include <cuda_fp16.h>
#include <math.h>
#include <stdint.h>

#define SEQ  2048
#define DM   4096
#define NH   16
#define DH   256
#define DFF  16384
#define LDQKV (3 * DM)

#define BM 128
#define BN 128
#define BK 32          // halves per k-step
#define STG 4
#define ROWH 40        // padded row length in halves (80B)
#define A_H (BM * ROWH)        // 5120 halves
#define B_H (BN * ROWH)        // 5120 halves
#define SLOT_H (A_H + B_H)     // 10240 halves
#define SLOT_B (SLOT_H * 2)    // 20480 bytes
#define SMEM_B (STG * SLOT_B)  // 81920 bytes -> 2 CTAs/SM

// ---- flash attention tiles (R9/R15-proven shape) ----
#define FBM 128                 // q rows per CTA work item
#define FBJ 64                  // keys per j-tile
#define FROWK 264               // Q/K smem row halves (256 + 8 pad)
#define FROWV 72                // V^T smem row halves (64 + 8 pad)
#define FQ_H (FBM * FROWK)      // 33792 halves
#define FK_H (FBJ * FROWK)      // 16896 halves per stage
#define FV_H (DH * FROWV)       // 18432 halves per stage
#define FK_BASE FQ_H
#define FV_BASE (FQ_H + 2 * FK_H)
#define FLASH_SMEM ((FQ_H + 2 * FK_H + 2 * FV_H) * 2)   // 208896 B

// ---------------- device scratch ----------------
__device__ __half g_xn [(size_t)SEQ * DM];
__device__ __half g_qkv[(size_t)SEQ * LDQKV];
__device__ __half g_vt [(size_t)DM * SEQ];          // v^T: [h*256+d][T]
__device__ __half g_av [(size_t)SEQ * DM];
__device__ float  g_ao [(size_t)SEQ * DM];
__device__ __half g_f1 [(size_t)SEQ * DFF];
// fp16 transposed weights [N][K]
__device__ __half g_wqkv[(size_t)LDQKV * DM];
__device__ __half g_wo  [(size_t)DM * DM];
__device__ __half g_w1t [(size_t)DFF * DM];
__device__ __half g_w2t [(size_t)DM * DFF];

// ---------------- helpers ----------------
__device__ __forceinline__ float gelu_f(float x) {
    float x3 = x * x * x;
    return x / (1.0f + __expf(-(1.5957691216057308f * x + 0.07135481627f * x3)));
}
__device__ __forceinline__ unsigned smem_u32(const void* p) {
    return (unsigned)__cvta_generic_to_shared(p);
}

#define CP_A16(saddr, gptr) \
    asm volatile("cp.async.cg.shared.global [%0], [%1], 16;\n" :: "r"(saddr), "l"(gptr))
#define CP_COMMIT() asm volatile("cp.async.commit_group;\n" ::: "memory")
#define CP_WAIT1()  asm volatile("cp.async.wait_group 1;\n" ::: "memory")
#define CP_WAIT2()  asm volatile("cp.async.wait_group 2;\n" ::: "memory")
#define CP_WAIT0()  asm volatile("cp.async.wait_group 0;\n" ::: "memory")

#define LDSM4(r, addr) \
    asm volatile("ldmatrix.sync.aligned.m8n8.x4.shared.b16 {%0,%1,%2,%3}, [%4];" \
        : "=r"((r)[0]), "=r"((r)[1]), "=r"((r)[2]), "=r"((r)[3]) : "r"(addr))

__device__ __forceinline__ void mma16(float c[4], const uint32_t a[4], uint32_t b0, uint32_t b1) {
    asm volatile(
        "mma.sync.aligned.m16n8k16.row.col.f32.f16.f16.f32 "
        "{%0,%1,%2,%3},{%4,%5,%6,%7},{%8,%9},{%0,%1,%2,%3};"
        : "+f"(c[0]), "+f"(c[1]), "+f"(c[2]), "+f"(c[3])
        : "r"(a[0]), "r"(a[1]), "r"(a[2]), "r"(a[3]), "r"(b0), "r"(b1));
}

template <typename T> __device__ __forceinline__ void store2(T* p, float x, float y);
template <> __device__ __forceinline__ void store2<float>(float* p, float x, float y) {
    *(float2*)p = make_float2(x, y);
}
template <> __device__ __forceinline__ void store2<__half>(__half* p, float x, float y) {
    *(__half2*)p = __floats2half2_rn(x, y);
}

// ================= FP16 GEMM: C[M][N] = A[M][K] @ BT[N][K]^T (R10-proven) =================
template <int EPI, typename OutT>
__global__ __launch_bounds__(128, 2)
void gemm16(const __half* __restrict__ A, const __half* __restrict__ BT,
            OutT* __restrict__ C, int K, int lda, int ldb, int ldc,
            const float* __restrict__ bias, const float* __restrict__ addend) {
    extern __shared__ __half smh[];
    int m0 = blockIdx.y * BM, n0 = blockIdx.x * BN;
    int tid = threadIdx.x, warp = tid >> 5, lane = tid & 31;
    int nk = K / BK;

    uint32_t sb = smem_u32(smh);
    const __half* Ag = A + (size_t)(m0 + (tid >> 2)) * lda + (tid & 3) * 8;
    const __half* Bg = BT + (size_t)(n0 + (tid >> 2)) * ldb + (tid & 3) * 8;
    uint32_t Ad = sb + ((tid >> 2) * ROWH + (tid & 3) * 8) * 2;
    uint32_t Bd = sb + (A_H + (tid >> 2) * ROWH + (tid & 3) * 8) * 2;

    auto issue = [&](int t) {
        uint32_t off = (t & 3) * SLOT_B;
        int k0 = t * BK;
#pragma unroll
        for (int i = 0; i < 4; i++)
            CP_A16(Ad + off + i * 32 * ROWH * 2, Ag + (size_t)i * 32 * lda + k0);
#pragma unroll
        for (int i = 0; i < 4; i++)
            CP_A16(Bd + off + i * 32 * ROWH * 2, Bg + (size_t)i * 32 * ldb + k0);
    };

    issue(0); CP_COMMIT();
    if (nk > 1) issue(1);
    CP_COMMIT();
    if (nk > 2) issue(2);
    CP_COMMIT();

    int wm = (warp >> 1) * 64, wn = (warp & 1) * 64;
    uint32_t aAddr = sb + ((wm + (lane & 15)) * ROWH + (lane >> 4) * 8) * 2;
    uint32_t bAddr = sb + A_H * 2 +
                     ((wn + (lane & 7) + ((lane >> 4) & 1) * 8) * ROWH + ((lane >> 3) & 1) * 8) * 2;

    float acc[4][8][4];
#pragma unroll
    for (int i = 0; i < 4; i++)
#pragma unroll
        for (int j = 0; j < 8; j++)
#pragma unroll
            for (int q = 0; q < 4; q++) acc[i][j][q] = 0.f;

    for (int t = 0; t < nk; t++) {
        CP_WAIT2();
        __syncthreads();
        int u = t + 3;
        if (u < nk) issue(u);
        CP_COMMIT();

        uint32_t so = (t & 3) * SLOT_B;
#pragma unroll
        for (int ks = 0; ks < 2; ks++) {
            uint32_t a[4][4], b[4][4];
#pragma unroll
            for (int mt = 0; mt < 4; mt++)
                LDSM4(a[mt], aAddr + so + mt * (16 * ROWH * 2) + ks * 32);
#pragma unroll
            for (int p = 0; p < 4; p++)
                LDSM4(b[p], bAddr + so + p * (16 * ROWH * 2) + ks * 32);
#pragma unroll
            for (int mt = 0; mt < 4; mt++)
#pragma unroll
                for (int nt = 0; nt < 8; nt++)
                    mma16(acc[mt][nt], a[mt], b[nt >> 1][(nt & 1) * 2], b[nt >> 1][(nt & 1) * 2 + 1]);
        }
    }

    CP_WAIT0();
    __syncthreads();

    int r = lane >> 2, c2 = 2 * (lane & 3);
#pragma unroll
    for (int mt = 0; mt < 4; mt++)
#pragma unroll
        for (int nt = 0; nt < 8; nt++) {
            int gm0 = m0 + wm + mt * 16 + r;
            int gn = n0 + wn + nt * 8 + c2;
#pragma unroll
            for (int h = 0; h < 2; h++) {
                int gm = gm0 + h * 8;
                float vx = acc[mt][nt][h * 2], vy = acc[mt][nt][h * 2 + 1];
                if (EPI == 2 || EPI == 3) {
                    const float2 bb = *(const float2*)(bias + gn);
                    vx += bb.x; vy += bb.y;
                }
                if (EPI == 2) { vx = gelu_f(vx); vy = gelu_f(vy); }
                if (EPI == 3) {
                    const float2 ad = *(const float2*)(addend + (size_t)gm * ldc + gn);
                    vx += ad.x; vy += ad.y;
                }
                store2<OutT>(C + (size_t)gm * ldc + gn, vx, vy);
            }
        }
}

// ================= fused flash attention (LPT-paired work items, R9/R15-proven) =================
__global__ __launch_bounds__(256, 1)
void flash16(const __half* __restrict__ qkv, const __half* __restrict__ vt,
             const float* __restrict__ ab, __half* __restrict__ av) {
    int h = blockIdx.y;
    extern __shared__ __half smh[];
    uint32_t sb = smem_u32(smh);
    int tid = threadIdx.x, warp = tid >> 5, lane = tid & 31;

    const __half* Kg = qkv + DM + (size_t)h * DH;
    const __half* Vg = vt + (size_t)h * DH * SEQ;
    const __half* Qg = qkv + (size_t)h * DH;

    int nmt = SEQ / FBM;                      // 16

    for (int item = 0; item < 2; item++) {
        int mt = item == 0 ? (nmt - 1 - (int)blockIdx.x) : (int)blockIdx.x;
        int m0 = mt * FBM;
        int nj = (m0 + FBM) / FBJ;

        __syncthreads();   // all warps done reading smem from previous item

        {
            int row = tid >> 1, cb = (tid & 1) * 16;
#pragma unroll
            for (int i = 0; i < 16; i++) {
                int ch = cb + i;
                CP_A16(sb + (row * FROWK + ch * 8) * 2,
                       Qg + (size_t)(m0 + row) * LDQKV + ch * 8);
            }
        }

        auto issue = [&](int t) {
            int buf = t & 1;
            int j0 = t * FBJ;
            int krow = tid >> 2, kc0 = (tid & 3) * 8;
#pragma unroll
            for (int i = 0; i < 8; i++) {
                int ch = kc0 + i;
                CP_A16(sb + (FK_BASE + buf * FK_H + krow * FROWK + ch * 8) * 2,
                       Kg + (size_t)(j0 + krow) * LDQKV + ch * 8);
            }
            int vr = tid >> 1, vc0 = (tid & 1) * 4;
#pragma unroll
            for (int i = 0; i < 8; i++) {
                int rr = vr + (i >> 2) * 128;
                int ch = vc0 + (i & 3);
                CP_A16(sb + (FV_BASE + buf * FV_H + rr * FROWV + ch * 8) * 2,
                       Vg + (size_t)rr * SEQ + j0 + ch * 8);
            }
        };

        issue(0); CP_COMMIT();
        if (nj > 1) issue(1);
        CP_COMMIT();

        float o[32][4];
#pragma unroll
        for (int i = 0; i < 32; i++)
#pragma unroll
            for (int q = 0; q < 4; q++) o[i][q] = 0.f;
        float mrun0 = -1e30f, mrun1 = -1e30f;
        float lrun0 = 0.f, lrun1 = 0.f;

        uint32_t aQ = sb + ((16 * warp + (lane & 15)) * FROWK + (lane >> 4) * 8) * 2;
        int r = lane >> 2, c = lane & 3;
        int row0 = m0 + 16 * warp + r;
        const float scl = 1.0f / 16.0f;

        for (int t = 0; t < nj; t++) {
            CP_WAIT1();
            __syncthreads();
            int j0 = t * FBJ;
            uint32_t kb = sb + (FK_BASE + (t & 1) * FK_H) * 2;
            uint32_t vb = sb + (FV_BASE + (t & 1) * FV_H) * 2;

            float s[8][4];
#pragma unroll
            for (int nt = 0; nt < 8; nt++)
#pragma unroll
                for (int q = 0; q < 4; q++) s[nt][q] = 0.f;
#pragma unroll 4
            for (int ks = 0; ks < 16; ks++) {
                uint32_t aq[4];
                LDSM4(aq, aQ + ks * 32);
#pragma unroll
                for (int p = 0; p < 4; p++) {
                    uint32_t bk[4];
                    LDSM4(bk, kb + ((p * 16 + (lane & 7) + ((lane >> 4) & 1) * 8) * FROWK
                                    + ((lane >> 3) & 1) * 8 + ks * 16) * 2);
                    mma16(s[2 * p],     aq, bk[0], bk[1]);
                    mma16(s[2 * p + 1], aq, bk[2], bk[3]);
                }
            }

            bool domask = (t >= nj - 2);
            float rmax0 = -1e30f, rmax1 = -1e30f;
#pragma unroll
            for (int nt = 0; nt < 8; nt++) {
                int j = j0 + nt * 8 + 2 * c;
                const float2 b0 = *(const float2*)(ab + (size_t)row0 * SEQ + j);
                const float2 b1 = *(const float2*)(ab + (size_t)(row0 + 8) * SEQ + j);
                s[nt][0] = s[nt][0] * scl + b0.x;
                s[nt][1] = s[nt][1] * scl + b0.y;
                s[nt][2] = s[nt][2] * scl + b1.x;
                s[nt][3] = s[nt][3] * scl + b1.y;
                if (domask) {
                    if (j     > row0)     s[nt][0] = -1e30f;
                    if (j + 1 > row0)     s[nt][1] = -1e30f;
                    if (j     > row0 + 8) s[nt][2] = -1e30f;
                    if (j + 1 > row0 + 8) s[nt][3] = -1e30f;
                }
                rmax0 = fmaxf(rmax0, fmaxf(s[nt][0], s[nt][1]));
                rmax1 = fmaxf(rmax1, fmaxf(s[nt][2], s[nt][3]));
            }
            rmax0 = fmaxf(rmax0, __shfl_xor_sync(0xffffffffu, rmax0, 1));
            rmax0 = fmaxf(rmax0, __shfl_xor_sync(0xffffffffu, rmax0, 2));
            rmax1 = fmaxf(rmax1, __shfl_xor_sync(0xffffffffu, rmax1, 1));
            rmax1 = fmaxf(rmax1, __shfl_xor_sync(0xffffffffu, rmax1, 2));
            float mnew0 = fmaxf(mrun0, rmax0);
            float mnew1 = fmaxf(mrun1, rmax1);
            float corr0 = __expf(mrun0 - mnew0);
            float corr1 = __expf(mrun1 - mnew1);
            mrun0 = mnew0; mrun1 = mnew1;

            uint32_t ph[8][2];
            float rs0 = 0.f, rs1 = 0.f;
#pragma unroll
            for (int nt = 0; nt < 8; nt++) {
                float p0 = __expf(s[nt][0] - mnew0);
                float p1 = __expf(s[nt][1] - mnew0);
                float p2 = __expf(s[nt][2] - mnew1);
                float p3 = __expf(s[nt][3] - mnew1);
                rs0 += p0 + p1; rs1 += p2 + p3;
                __half2 h0 = __floats2half2_rn(p0, p1);
                __half2 h1 = __floats2half2_rn(p2, p3);
                ph[nt][0] = *(uint32_t*)&h0;
                ph[nt][1] = *(uint32_t*)&h1;
            }
            rs0 += __shfl_xor_sync(0xffffffffu, rs0, 1);
            rs0 += __shfl_xor_sync(0xffffffffu, rs0, 2);
            rs1 += __shfl_xor_sync(0xffffffffu, rs1, 1);
            rs1 += __shfl_xor_sync(0xffffffffu, rs1, 2);
            lrun0 = lrun0 * corr0 + rs0;
            lrun1 = lrun1 * corr1 + rs1;
#pragma unroll
            for (int p = 0; p < 32; p++) {
                o[p][0] *= corr0; o[p][1] *= corr0;
                o[p][2] *= corr1; o[p][3] *= corr1;
            }

#pragma unroll
            for (int kk = 0; kk < 4; kk++) {
                uint32_t a[4] = { ph[2 * kk][0], ph[2 * kk][1], ph[2 * kk + 1][0], ph[2 * kk + 1][1] };
#pragma unroll
                for (int p = 0; p < 16; p++) {
                    uint32_t bv[4];
                    LDSM4(bv, vb + ((p * 16 + (lane & 7) + ((lane >> 4) & 1) * 8) * FROWV
                                    + ((lane >> 3) & 1) * 8 + kk * 16) * 2);
                    mma16(o[2 * p],     a, bv[0], bv[1]);
                    mma16(o[2 * p + 1], a, bv[2], bv[3]);
                }
            }

            __syncthreads();
            if (t + 2 < nj) issue(t + 2);
            CP_COMMIT();
        }

        float inv0 = 1.0f / lrun0, inv1 = 1.0f / lrun1;
        __half* a0 = av + (size_t)row0 * DM + h * DH;
        __half* a1 = av + (size_t)(row0 + 8) * DM + h * DH;
#pragma unroll
        for (int p = 0; p < 32; p++) {
            int d = p * 8 + 2 * c;
            *(__half2*)(a0 + d) = __floats2half2_rn(o[p][0] * inv0, o[p][1] * inv0);
            *(__half2*)(a1 + d) = __floats2half2_rn(o[p][2] * inv1, o[p][3] * inv1);
        }
        CP_WAIT0();   // drain any trailing empty groups before reusing smem
    }
}

// ================= fused 4-way weight transpose (DM x DM each): z selects matrix =================
__global__ __launch_bounds__(256)
void trw4(const float* __restrict__ s0, const float* __restrict__ s1q,
          const float* __restrict__ s2, const float* __restrict__ s3,
          __half* __restrict__ d0, __half* __restrict__ d1,
          __half* __restrict__ d2, __half* __restrict__ d3) {
    const float* src = (blockIdx.z == 0) ? s0 : (blockIdx.z == 1) ? s1q : (blockIdx.z == 2) ? s2 : s3;
    __half* dst = (blockIdx.z == 0) ? d0 : (blockIdx.z == 1) ? d1 : (blockIdx.z == 2) ? d2 : d3;
    __shared__ float tile[64][33];
    int k0 = blockIdx.y * 64, n0 = blockIdx.x * 32;
    int tx = threadIdx.x, ty = threadIdx.y;
#pragma unroll
    for (int i = 0; i < 8; i++)
        tile[ty + i * 8][tx] = src[(size_t)(k0 + ty + i * 8) * DM + n0 + tx];
    __syncthreads();
#pragma unroll
    for (int i = 0; i < 4; i++) {
        int n = ty + i * 8;
        __half2 h = __floats2half2_rn(tile[2 * tx][n], tile[2 * tx + 1][n]);
        *(__half2*)(dst + (size_t)(n0 + n) * DM + k0 + 2 * tx) = h;
    }
}

// ================= weight transpose + fp32->fp16 (R10-proven; for w1/w2) =================
__global__ __launch_bounds__(256)
void trw(const float* __restrict__ src, __half* __restrict__ dst, int K, int N) {
    __shared__ float tile[64][33];
    int k0 = blockIdx.y * 64, n0 = blockIdx.x * 32;
    int tx = threadIdx.x, ty = threadIdx.y;
#pragma unroll
    for (int i = 0; i < 8; i++)
        tile[ty + i * 8][tx] = src[(size_t)(k0 + ty + i * 8) * N + n0 + tx];
    __syncthreads();
#pragma unroll
    for (int i = 0; i < 4; i++) {
        int n = ty + i * 8;
        __half2 h = __floats2half2_rn(tile[2 * tx][n], tile[2 * tx + 1][n]);
        *(__half2*)(dst + (size_t)(n0 + n) * K + k0 + 2 * tx) = h;
    }
}

// ================= v transpose (R5-proven): vt[c][T] = qkv[T][2*DM + c] =================
__global__ void trv(const __half* __restrict__ qkv, __half* __restrict__ vt) {
    __shared__ __half tile[32][33];
    int c0 = blockIdx.x * 32, T0 = blockIdx.y * 32;
    int tx = threadIdx.x, ty = threadIdx.y;
#pragma unroll
    for (int i = 0; i < 4; i++)
        tile[ty + i * 8][tx] = qkv[(size_t)(T0 + ty + i * 8) * LDQKV + 2 * DM + c0 + tx];
    __syncthreads();
#pragma unroll
    for (int i = 0; i < 4; i++)
        vt[(size_t)(c0 + ty + i * 8) * SEQ + T0 + tx] = tile[tx][ty + i * 8];
}

// ================= layernorm -> half (single-pass, register-cached; R15-proven) =================
__global__ void ln_kernel(const float* __restrict__ x, const float* __restrict__ sc,
                          const float* __restrict__ of, __half* __restrict__ xn) {
    int row = blockIdx.x;
    const float4* xr = (const float4*)(x + (size_t)row * DM);
    __half* xo = xn + (size_t)row * DM;
    __shared__ float redS[256];
    __shared__ float redQ[256];
    int tid = threadIdx.x;

    float4 v[4];
    float s = 0.f, q = 0.f;
#pragma unroll
    for (int i = 0; i < 4; i++) {
        v[i] = xr[tid + i * 256];
        s += v[i].x + v[i].y + v[i].z + v[i].w;
        q += v[i].x * v[i].x + v[i].y * v[i].y + v[i].z * v[i].z + v[i].w * v[i].w;
    }
    redS[tid] = s; redQ[tid] = q;
    __syncthreads();
    for (int st = 128; st > 0; st >>= 1) {
        if (tid < st) { redS[tid] += redS[tid + st]; redQ[tid] += redQ[tid + st]; }
        __syncthreads();
    }
    float mean = redS[0] * (1.0f / DM);
    float var = redQ[0] * (1.0f / DM) - mean * mean;
    float rstd = rsqrtf(var + 1e-5f);

#pragma unroll
    for (int i = 0; i < 4; i++) {
        int base = (tid + i * 256) * 4;
        const float4 g = *(const float4*)(sc + base);
        const float4 o = *(const float4*)(of + base);
        __half2 h0 = __floats2half2_rn(g.x * rstd * (v[i].x - mean) + o.x,
                                       g.y * rstd * (v[i].y - mean) + o.y);
        __half2 h1 = __floats2half2_rn(g.z * rstd * (v[i].z - mean) + o.z,
                                       g.w * rstd * (v[i].w - mean) + o.w);
        uint2 pk = make_uint2(*(uint32_t*)&h0, *(uint32_t*)&h1);
        *(uint2*)(xo + base) = pk;
    }
}

// ================= RoPE on half q,k =================
__global__ void rope_kernel(__half* __restrict__ qkv) {
    int t = blockIdx.x, tid = threadIdx.x;
    __shared__ float ss[32], cc[32];
    if (tid < 32) {
        double inv = pow(10000.0, -((double)(2 * tid)) / 64.0);
        double a = (double)t * inv;
        ss[tid] = (float)sin(a); cc[tid] = (float)cos(a);
    }
    __syncthreads();
    int head = tid >> 5, i = tid & 31;
    float s = ss[i], co = cc[i];
    size_t qoff = (size_t)t * LDQKV + head * DH + 2 * i;
    size_t koff = qoff + DM;
    float q0 = __half2float(qkv[qoff]), q1 = __half2float(qkv[qoff + 1]);
    qkv[qoff]     = __float2half(q0 * co - q1 * s);
    qkv[qoff + 1] = __float2half(q1 * co + q0 * s);
    float k0 = __half2float(qkv[koff]), k1 = __half2float(qkv[koff + 1]);
    qkv[koff]     = __float2half(k0 * co - k1 * s);
    qkv[koff + 1] = __float2half(k1 * co + k0 * s);
}

// ================= launch (R10/R15 schedule; 4 DMxDM transposes fused) =================
extern "C" void kernel_launch(void* const* d_in, const int* in_sizes, int n_in,
                              void* d_out, int out_size) {
    const float* x   = (const float*)d_in[0];
    const float* ab  = (const float*)d_in[1];
    const float* lns = (const float*)d_in[2];
    const float* lno = (const float*)d_in[3];
    const float* wq  = (const float*)d_in[4];
    const float* wk  = (const float*)d_in[5];
    const float* wv  = (const float*)d_in[6];
    const float* wo  = (const float*)d_in[7];
    const float* w1  = (const float*)d_in[8];
    const float* b1  = (const float*)d_in[9];
    const float* w2  = (const float*)d_in[10];
    const float* b2  = (const float*)d_in[11];
    float* out = (float*)d_out;

    __half *xn, *qkv, *vt, *av, *f1, *wqkv16, *wo16, *w1t16, *w2t16;
    float *ao;
    cudaGetSymbolAddress((void**)&xn,     g_xn);
    cudaGetSymbolAddress((void**)&qkv,    g_qkv);
    cudaGetSymbolAddress((void**)&vt,     g_vt);
    cudaGetSymbolAddress((void**)&av,     g_av);
    cudaGetSymbolAddress((void**)&ao,     g_ao);
    cudaGetSymbolAddress((void**)&f1,     g_f1);
    cudaGetSymbolAddress((void**)&wqkv16, g_wqkv);
    cudaGetSymbolAddress((void**)&wo16,   g_wo);
    cudaGetSymbolAddress((void**)&w1t16,  g_w1t);
    cudaGetSymbolAddress((void**)&w2t16,  g_w2t);

    cudaFuncSetAttribute(gemm16<0, __half>, cudaFuncAttributeMaxDynamicSharedMemorySize, SMEM_B);
    cudaFuncSetAttribute(gemm16<0, float>,  cudaFuncAttributeMaxDynamicSharedMemorySize, SMEM_B);
    cudaFuncSetAttribute(gemm16<2, __half>, cudaFuncAttributeMaxDynamicSharedMemorySize, SMEM_B);
    cudaFuncSetAttribute(gemm16<3, float>,  cudaFuncAttributeMaxDynamicSharedMemorySize, SMEM_B);
    cudaFuncSetAttribute(flash16,           cudaFuncAttributeMaxDynamicSharedMemorySize, FLASH_SMEM);

    // fork/join: FFN-hidden branch on s1, attention branch on the capture (default) stream
    cudaStream_t s1;
    cudaStreamCreateWithFlags(&s1, cudaStreamNonBlocking);
    cudaEvent_t evRoot, evLN, evF1;
    cudaEventCreateWithFlags(&evRoot, cudaEventDisableTiming);
    cudaEventCreateWithFlags(&evLN,   cudaEventDisableTiming);
    cudaEventCreateWithFlags(&evF1,   cudaEventDisableTiming);

    dim3 tb(32, 8);
    cudaEventRecord(evRoot, 0);
    cudaStreamWaitEvent(s1, evRoot, 0);

    // ---- s1 branch: w1/w2 prep, then FFN1 after LN ----
    trw<<<dim3(DFF / 32, DM / 64), tb, 0, s1>>>(w1, w1t16, DM, DFF);
    trw<<<dim3(DM / 32, DFF / 64), tb, 0, s1>>>(w2, w2t16, DFF, DM);

    // ---- s0: attention-side weight prep (fused 4-way) + LN ----
    trw4<<<dim3(DM / 32, DM / 64, 4), tb>>>(
        wq, wk, wv, wo,
        wqkv16, wqkv16 + (size_t)DM * DM, wqkv16 + (size_t)2 * DM * DM, wo16);
    ln_kernel<<<SEQ, 256>>>(x, lns, lno, xn);
    cudaEventRecord(evLN, 0);

    // s1: FFN1 after LN
    cudaStreamWaitEvent(s1, evLN, 0);
    gemm16<2, __half><<<dim3(DFF / BN, SEQ / BM), 128, SMEM_B, s1>>>(
        xn, w1t16, f1, DM, DM, DM, DFF, b1, nullptr);
    cudaEventRecord(evF1, s1);

    // ---- s0: attention chain ----
    gemm16<0, __half><<<dim3(LDQKV / BN, SEQ / BM), 128, SMEM_B>>>(
        xn, wqkv16, qkv, DM, DM, DM, LDQKV, nullptr, nullptr);
    rope_kernel<<<SEQ, 512>>>(qkv);
    trv<<<dim3(DM / 32, SEQ / 32), tb>>>(qkv, vt);
    flash16<<<dim3(SEQ / FBM / 2, NH), 256, FLASH_SMEM>>>(qkv, vt, ab, av);
    gemm16<0, float><<<dim3(DM / BN, SEQ / BM), 128, SMEM_B>>>(
        av, wo16, ao, DM, DM, DM, DM, nullptr, nullptr);

    // join and final FFN2 (+bias +residual)
    cudaStreamWaitEvent(0, evF1, 0);
    gemm16<3, float><<<dim3(DM / BN, SEQ / BM), 128, SMEM_B>>>(
        f1, w2t16, out, DFF, DFF, DFF, DM, b2, ao);
}